// round 10
// baseline (speedup 1.0000x reference)
#include <cuda_runtime.h>

typedef unsigned long long ull;

#define NB_B   4096
#define NB_S   128
#define NB_D   9
#define NB_V   5
#define NB_BLK 4

// log2(e)/3 : folds softmax scale (1/sqrt(9)) and exp->exp2 into Wq/bq
#define QSCL   0.48089834696298784f

// ---------- packed f32x2 helpers (Blackwell sm_103a) ----------
__device__ __forceinline__ ull pack2(float a, float b) {
    ull r; asm("mov.b64 %0, {%1,%2};" : "=l"(r) : "f"(a), "f"(b)); return r;
}
__device__ __forceinline__ void unpack2(ull v, float& a, float& b) {
    asm("mov.b64 {%0,%1}, %2;" : "=f"(a), "=f"(b) : "l"(v));
}
__device__ __forceinline__ ull fma2(ull a, ull b, ull c) {
    ull d; asm("fma.rn.f32x2 %0, %1, %2, %3;" : "=l"(d) : "l"(a), "l"(b), "l"(c)); return d;
}
__device__ __forceinline__ ull mul2(ull a, ull b) {
    ull d; asm("mul.rn.f32x2 %0, %1, %2;" : "=l"(d) : "l"(a), "l"(b)); return d;
}
__device__ __forceinline__ ull add2(ull a, ull b) {
    ull d; asm("add.rn.f32x2 %0, %1, %2;" : "=l"(d) : "l"(a), "l"(b)); return d;
}
__device__ __forceinline__ float ex2f(float x) {
    float y; asm("ex2.approx.f32 %0, %1;" : "=f"(y) : "f"(x)); return y;
}

// packed-weight row (10 ull: w0..w8 duplicated + bias pair) vs packed-x pair.
// 5 LDS.128 + 9 fma2, zero MOVs.
__device__ __forceinline__ ull projd(const ull* __restrict__ wrow, const ull x[NB_D]) {
    ulonglong2 p0 = *(const ulonglong2*)(wrow);
    ulonglong2 p1 = *(const ulonglong2*)(wrow + 2);
    ulonglong2 p2 = *(const ulonglong2*)(wrow + 4);
    ulonglong2 p3 = *(const ulonglong2*)(wrow + 6);
    ulonglong2 p4 = *(const ulonglong2*)(wrow + 8);   // (w8, bias)
    ull t = p4.y;
    t = fma2(p0.x, x[0], t);
    t = fma2(p0.y, x[1], t);
    t = fma2(p1.x, x[2], t);
    t = fma2(p1.y, x[3], t);
    t = fma2(p2.x, x[4], t);
    t = fma2(p2.y, x[5], t);
    t = fma2(p3.x, x[6], t);
    t = fma2(p3.y, x[7], t);
    t = fma2(p4.x, x[8], t);
    return t;
}

__global__ __launch_bounds__(64, 10)
void bert_kernel(const int*   __restrict__ tokens,
                 const float* __restrict__ emb,
                 const float* __restrict__ Wq, const float* __restrict__ bq,
                 const float* __restrict__ Wk, const float* __restrict__ bk,
                 const float* __restrict__ Wv, const float* __restrict__ bv,
                 const float* __restrict__ Wout, const float* __restrict__ bout,
                 float* __restrict__ out)
{
    // ONE batch per 64-thread CTA (2 warps); K and V transposed scalar
    __shared__ __align__(16) float sKt[NB_D][NB_S];          // 4608 B  [d][k]
    __shared__ __align__(16) float sVt[NB_D][NB_S];          // 4608 B  [d][k]
    // pre-duplicated weight rows: [blk][q/k/v][e] = {(w0,w0)..(w8,w8),(b,b)}
    __shared__ __align__(16) ull sWd[NB_BLK][3][NB_D][10];   // 8640 B
    __shared__ __align__(16) ull sWoutd[NB_V][10];           // 400 B
    __shared__ __align__(16) float sEmb[NB_V][12];           // 240 B
    // ~18.5 KB total

    const int tid  = threadIdx.x;
    const int wh   = tid >> 5;       // query half (0..1)
    const int lane = tid & 31;
    const int b    = blockIdx.x;

    // ---- cooperative weight load: duplicate into (w,w) pairs ----
    // 4*3*9 = 108 rows of 9 weights; Wq/bq pre-scaled into exp2 domain
    for (int idx = tid; idx < NB_BLK * NB_D * NB_D; idx += 64) {
        int i = idx / (NB_D * NB_D);
        int r = idx % (NB_D * NB_D);
        int e = r / NB_D, d = r % NB_D;
        float wq = Wq[idx] * QSCL;
        float wk = Wk[idx];
        float wv = Wv[idx];
        sWd[i][0][e][d] = pack2(wq, wq);
        sWd[i][1][e][d] = pack2(wk, wk);
        sWd[i][2][e][d] = pack2(wv, wv);
    }
    for (int idx = tid; idx < NB_BLK * NB_D; idx += 64) {
        int i = idx / NB_D, e = idx % NB_D;
        float vq = bq[idx] * QSCL;
        float vk = bk[idx];
        float vv = bv[idx];
        sWd[i][0][e][9] = pack2(vq, vq);
        sWd[i][1][e][9] = pack2(vk, vk);
        sWd[i][2][e][9] = pack2(vv, vv);
    }
    if (tid < NB_V * NB_D) {
        int v = tid / NB_D, d = tid % NB_D;
        float wo = Wout[tid];
        sWoutd[v][d] = pack2(wo, wo);
        sEmb[v][d]   = emb[tid];
    }
    if (tid < NB_V) {
        float bo = bout[tid];
        sWoutd[tid][9] = pack2(bo, bo);
    }
    __syncthreads();

    // ---- x for this lane's 2 positions: (posA, posB) = (wh*64+lane, +32) ----
    const int posA = wh * 64 + lane;
    const int posB = posA + 32;
    ull x2[NB_D];
    {
        const float L2_1E4 = 13.287712379549449f;
        int tokA = tokens[b * NB_S + posA];
        int tokB = tokens[b * NB_S + posB];
        #pragma unroll
        for (int d = 0; d < NB_D; ++d) {
            float ex   = (float)(2 * (d >> 1)) * (1.0f / 9.0f);
            float invf = exp2f(-ex * L2_1E4);
            float angA = (float)posA * invf;
            float angB = (float)posB * invf;
            float peA  = ((d & 1) == 0) ? sinf(angA) : cosf(angA);
            float peB  = ((d & 1) == 0) ? sinf(angB) : cosf(angB);
            x2[d] = pack2(sEmb[tokA][d] + peA, sEmb[tokB][d] + peB);
        }
    }

    #pragma unroll 1
    for (int blk = 0; blk < NB_BLK; ++blk) {
        // ---- QKV projection (MOV-free); K/V written transposed scalar ----
        ull q2[NB_D];
        #pragma unroll
        for (int e = 0; e < NB_D; ++e) {
            q2[e]  = projd(&sWd[blk][0][e][0], x2);
            ull kk = projd(&sWd[blk][1][e][0], x2);
            ull vv = projd(&sWd[blk][2][e][0], x2);
            float a, bb;
            unpack2(kk, a, bb);
            sKt[e][posA] = a;  sKt[e][posB] = bb;
            unpack2(vv, a, bb);
            sVt[e][posA] = a;  sVt[e][posB] = bb;
        }
        __syncthreads();

        // duplicated queries in registers (18 MOVs per block, cold)
        ull qa[NB_D], qb[NB_D];
        #pragma unroll
        for (int d = 0; d < NB_D; ++d) {
            float a, bb; unpack2(q2[d], a, bb);
            qa[d] = pack2(a, a);
            qb[d] = pack2(bb, bb);
        }

        // ---- single-pass attention; acc packed over KEY pairs (no dup MOVs) ----
        ull acc0[NB_D], acc1[NB_D];     // acc0: query A, acc1: query B
        #pragma unroll
        for (int d = 0; d < NB_D; ++d) { acc0[d] = 0ULL; acc1[d] = 0ULL; }
        ull den0 = 0ULL, den1 = 0ULL;   // packed over key pairs

        #pragma unroll 4
        for (int g = 0; g < NB_S / 4; ++g) {
            // scores packed over key pairs (keys 4g..4g+3)
            ull s00, s01, s10, s11;
            {
                const ulonglong2 kk0 = *(const ulonglong2*)&sKt[0][g*4];
                s00 = mul2(kk0.x, qa[0]); s01 = mul2(kk0.y, qa[0]);
                s10 = mul2(kk0.x, qb[0]); s11 = mul2(kk0.y, qb[0]);
            }
            #pragma unroll
            for (int d = 1; d < NB_D; ++d) {
                const ulonglong2 kk = *(const ulonglong2*)&sKt[d][g*4];
                s00 = fma2(kk.x, qa[d], s00); s01 = fma2(kk.y, qa[d], s01);
                s10 = fma2(kk.x, qb[d], s10); s11 = fma2(kk.y, qb[d], s11);
            }
            float sa0, sa1, sa2, sa3, sb0, sb1, sb2, sb3;
            unpack2(s00, sa0, sa1);
            unpack2(s01, sa2, sa3);
            unpack2(s10, sb0, sb1);
            unpack2(s11, sb2, sb3);
            // exp2, packed over keys (pairs of fresh values -> no copy MOVs)
            ull ep00 = pack2(ex2f(sa0), ex2f(sa1));   // query A, keys 0,1
            ull ep01 = pack2(ex2f(sa2), ex2f(sa3));   // query A, keys 2,3
            ull ep10 = pack2(ex2f(sb0), ex2f(sb1));   // query B, keys 0,1
            ull ep11 = pack2(ex2f(sb2), ex2f(sb3));   // query B, keys 2,3
            den0 = add2(den0, add2(ep00, ep01));
            den1 = add2(den1, add2(ep10, ep11));
            // V reinterpreted as packed key pairs straight from smem
            #pragma unroll
            for (int d = 0; d < NB_D; ++d) {
                const ulonglong2 vv = *(const ulonglong2*)&sVt[d][g*4];
                acc0[d] = fma2(ep00, vv.x, acc0[d]);
                acc0[d] = fma2(ep01, vv.y, acc0[d]);
                acc1[d] = fma2(ep10, vv.x, acc1[d]);
                acc1[d] = fma2(ep11, vv.y, acc1[d]);
            }
        }

        // reduce packed-over-keys accumulators, normalize, repack over queries
        float da, db;
        unpack2(den0, da, db);
        float invA = __fdividef(1.f, da + db);
        unpack2(den1, da, db);
        float invB = __fdividef(1.f, da + db);
        #pragma unroll
        for (int d = 0; d < NB_D; ++d) {
            float a0, b0, a1, b1;
            unpack2(acc0[d], a0, b0);
            unpack2(acc1[d], a1, b1);
            x2[d] = pack2((a0 + b0) * invA, (a1 + b1) * invB);
        }

        __syncthreads();   // protect sKt/sVt before next block overwrites
    }

    // ---- output head: logits + log_softmax over V=5 (packed over posA/posB) ----
    ull lg2[NB_V];
    #pragma unroll
    for (int v = 0; v < NB_V; ++v)
        lg2[v] = projd(&sWoutd[v][0], x2);

    #pragma unroll
    for (int half = 0; half < 2; ++half) {
        int pos = half == 0 ? posA : posB;
        float lg[NB_V];
        #pragma unroll
        for (int v = 0; v < NB_V; ++v) {
            float a, bb; unpack2(lg2[v], a, bb);
            lg[v] = half == 0 ? a : bb;
        }
        float mx = lg[0];
        #pragma unroll
        for (int v = 1; v < NB_V; ++v) mx = fmaxf(mx, lg[v]);
        float sum = 0.f;
        #pragma unroll
        for (int v = 0; v < NB_V; ++v) sum += __expf(lg[v] - mx);
        float lse = mx + __logf(sum);
        float* o = out + ((size_t)b * NB_S + pos) * NB_V;
        #pragma unroll
        for (int v = 0; v < NB_V; ++v) o[v] = lg[v] - lse;
    }
}

extern "C" void kernel_launch(void* const* d_in, const int* in_sizes, int n_in,
                              void* d_out, int out_size)
{
    const int*   tokens = (const int*)  d_in[0];
    const float* emb    = (const float*)d_in[1];
    const float* Wq     = (const float*)d_in[2];
    const float* bq     = (const float*)d_in[3];
    const float* Wk     = (const float*)d_in[4];
    const float* bk     = (const float*)d_in[5];
    const float* Wv     = (const float*)d_in[6];
    const float* bv     = (const float*)d_in[7];
    const float* Wout   = (const float*)d_in[8];
    const float* bout   = (const float*)d_in[9];
    float* outp = (float*)d_out;

    bert_kernel<<<NB_B, 64>>>(tokens, emb, Wq, bq, Wk, bk, Wv, bv, Wout, bout, outp);
}

// round 11
// speedup vs baseline: 1.1064x; 1.1064x over previous
#include <cuda_runtime.h>

typedef unsigned long long ull;

#define NB_B   4096
#define NB_S   128
#define NB_D   9
#define NB_V   5
#define NB_BLK 4
#define RP     12

// log2(e)/3 : folds softmax scale (1/sqrt(9)) and exp->exp2 into Wq/bq
#define QSCL   0.48089834696298784f

// ---------- packed f32x2 helpers (Blackwell sm_103a) ----------
__device__ __forceinline__ ull pack2(float a, float b) {
    ull r; asm("mov.b64 %0, {%1,%2};" : "=l"(r) : "f"(a), "f"(b)); return r;
}
__device__ __forceinline__ void unpack2(ull v, float& a, float& b) {
    asm("mov.b64 {%0,%1}, %2;" : "=f"(a), "=f"(b) : "l"(v));
}
__device__ __forceinline__ ull fma2(ull a, ull b, ull c) {
    ull d; asm("fma.rn.f32x2 %0, %1, %2, %3;" : "=l"(d) : "l"(a), "l"(b), "l"(c)); return d;
}
__device__ __forceinline__ ull mul2(ull a, ull b) {
    ull d; asm("mul.rn.f32x2 %0, %1, %2;" : "=l"(d) : "l"(a), "l"(b)); return d;
}
__device__ __forceinline__ ull add2(ull a, ull b) {
    ull d; asm("add.rn.f32x2 %0, %1, %2;" : "=l"(d) : "l"(a), "l"(b)); return d;
}
__device__ __forceinline__ float ex2f(float x) {
    float y; asm("ex2.approx.f32 %0, %1;" : "=f"(y) : "f"(x)); return y;
}

// hardcoded inv_freq(d) = 10000^(-(2*(d//2))/9), removes runtime exp2f
__device__ __constant__ const float c_invf[NB_D] = {
    1.0f, 1.0f,
    1.2915497e-1f, 1.2915497e-1f,
    1.6681005e-2f, 1.6681005e-2f,
    2.1544347e-3f, 2.1544347e-3f,
    2.7825594e-4f
};

// scalar-weight row vs one packed-x pair (weights duplicated on the fly)
__device__ __forceinline__ ull proj1(const float* __restrict__ wrow, float bias,
                                     const ull x[NB_D]) {
    float4 a = *(const float4*)(wrow);
    float4 b = *(const float4*)(wrow + 4);
    float  c = wrow[8];
    ull t = pack2(bias, bias);
    t = fma2(pack2(a.x,a.x), x[0], t);
    t = fma2(pack2(a.y,a.y), x[1], t);
    t = fma2(pack2(a.z,a.z), x[2], t);
    t = fma2(pack2(a.w,a.w), x[3], t);
    t = fma2(pack2(b.x,b.x), x[4], t);
    t = fma2(pack2(b.y,b.y), x[5], t);
    t = fma2(pack2(b.z,b.z), x[6], t);
    t = fma2(pack2(b.w,b.w), x[7], t);
    t = fma2(pack2(c,c),     x[8], t);
    return t;
}

__global__ __launch_bounds__(64, 12)
void bert_kernel(const int*   __restrict__ tokens,
                 const float* __restrict__ emb,
                 const float* __restrict__ Wq, const float* __restrict__ bq,
                 const float* __restrict__ Wk, const float* __restrict__ bk,
                 const float* __restrict__ Wv, const float* __restrict__ bv,
                 const float* __restrict__ Wout, const float* __restrict__ bout,
                 float* __restrict__ out)
{
    // ONE batch per 64-thread CTA (2 warps); K and V transposed scalar
    __shared__ __align__(16) float sKt[NB_D][NB_S];          // 4608 B  [d][k]
    __shared__ __align__(16) float sVt[NB_D][NB_S];          // 4608 B  [d][k]
    __shared__ __align__(16) float sW[NB_BLK][3][NB_D][RP];  // 5184 B
    __shared__ float sB[NB_BLK][3][NB_D];                    // 432 B
    __shared__ __align__(16) float sWout[NB_V][RP];
    __shared__ __align__(16) float sEmb[NB_V][RP];
    __shared__ float sBout[NB_V];
    // ~15.3 KB total

    const int tid  = threadIdx.x;
    const int wh   = tid >> 5;       // query half (0..1)
    const int lane = tid & 31;
    const int b    = blockIdx.x;

    // ---- cooperative weight load (Wq/bq pre-scaled into exp2 domain) ----
    for (int idx = tid; idx < NB_BLK * NB_D * NB_D; idx += 64) {
        int i = idx / (NB_D * NB_D);
        int r = idx % (NB_D * NB_D);
        int e = r / NB_D, d = r % NB_D;
        sW[i][0][e][d] = Wq[idx] * QSCL;
        sW[i][1][e][d] = Wk[idx];
        sW[i][2][e][d] = Wv[idx];
    }
    for (int idx = tid; idx < NB_BLK * NB_D; idx += 64) {
        int i = idx / NB_D, e = idx % NB_D;
        sB[i][0][e] = bq[idx] * QSCL;
        sB[i][1][e] = bk[idx];
        sB[i][2][e] = bv[idx];
    }
    if (tid < NB_V * NB_D) {
        sWout[tid / NB_D][tid % NB_D] = Wout[tid];
        sEmb [tid / NB_D][tid % NB_D] = emb[tid];
    }
    if (tid < NB_V) sBout[tid] = bout[tid];
    __syncthreads();

    // ---- x for this lane's 2 positions: (posA, posB) = (wh*64+lane, +32) ----
    const int posA = wh * 64 + lane;
    const int posB = posA + 32;
    ull x2[NB_D];
    {
        int tokA = tokens[b * NB_S + posA];
        int tokB = tokens[b * NB_S + posB];
        #pragma unroll
        for (int d = 0; d < NB_D; ++d) {
            float angA = (float)posA * c_invf[d];
            float angB = (float)posB * c_invf[d];
            float peA  = ((d & 1) == 0) ? __sinf(angA) : __cosf(angA);
            float peB  = ((d & 1) == 0) ? __sinf(angB) : __cosf(angB);
            x2[d] = pack2(sEmb[tokA][d] + peA, sEmb[tokB][d] + peB);
        }
    }

    #pragma unroll 1
    for (int blk = 0; blk < NB_BLK; ++blk) {
        // ---- QKV projection; K/V written transposed scalar ----
        ull q2[NB_D];
        #pragma unroll
        for (int e = 0; e < NB_D; ++e) {
            q2[e]  = proj1(&sW[blk][0][e][0], sB[blk][0][e], x2);
            ull kk = proj1(&sW[blk][1][e][0], sB[blk][1][e], x2);
            ull vv = proj1(&sW[blk][2][e][0], sB[blk][2][e], x2);
            float a, bb;
            unpack2(kk, a, bb);
            sKt[e][posA] = a;  sKt[e][posB] = bb;
            unpack2(vv, a, bb);
            sVt[e][posA] = a;  sVt[e][posB] = bb;
        }
        __syncthreads();

        // duplicated queries in registers (for packed-over-key scores)
        ull qa[NB_D], qb[NB_D];
        #pragma unroll
        for (int d = 0; d < NB_D; ++d) {
            float a, bb; unpack2(q2[d], a, bb);
            qa[d] = pack2(a, a);
            qb[d] = pack2(bb, bb);
        }

        // ---- single-pass attention; accumulator packed over (qa,qb) ----
        ull acc[NB_D];
        #pragma unroll
        for (int d = 0; d < NB_D; ++d) acc[d] = 0ULL;
        ull den2 = 0ULL;

        #pragma unroll 4
        for (int g = 0; g < NB_S / 4; ++g) {
            // scores packed over key pairs (keys 4g .. 4g+3)
            ull s00, s01, s10, s11;
            {
                const ulonglong2 kk0 = *(const ulonglong2*)&sKt[0][g*4];
                s00 = mul2(kk0.x, qa[0]); s01 = mul2(kk0.y, qa[0]);
                s10 = mul2(kk0.x, qb[0]); s11 = mul2(kk0.y, qb[0]);
            }
            #pragma unroll
            for (int d = 1; d < NB_D; ++d) {
                const ulonglong2 kk = *(const ulonglong2*)&sKt[d][g*4];
                s00 = fma2(kk.x, qa[d], s00); s01 = fma2(kk.y, qa[d], s01);
                s10 = fma2(kk.x, qb[d], s10); s11 = fma2(kk.y, qb[d], s11);
            }
            float sa0, sa1, sa2, sa3, sb0, sb1, sb2, sb3;
            unpack2(s00, sa0, sa1);
            unpack2(s01, sa2, sa3);
            unpack2(s10, sb0, sb1);
            unpack2(s11, sb2, sb3);
            // exp2, repacked per-key over (qa,qb)
            ull ep0 = pack2(ex2f(sa0), ex2f(sb0));
            ull ep1 = pack2(ex2f(sa1), ex2f(sb1));
            ull ep2 = pack2(ex2f(sa2), ex2f(sb2));
            ull ep3 = pack2(ex2f(sa3), ex2f(sb3));
            den2 = add2(den2, add2(add2(ep0, ep1), add2(ep2, ep3)));
            // V accumulation: acc packed over queries, V duplicated on the fly (alu pipe)
            #pragma unroll
            for (int d = 0; d < NB_D; ++d) {
                const float4 v = *(const float4*)&sVt[d][g*4];
                acc[d] = fma2(ep0, pack2(v.x, v.x), acc[d]);
                acc[d] = fma2(ep1, pack2(v.y, v.y), acc[d]);
                acc[d] = fma2(ep2, pack2(v.z, v.z), acc[d]);
                acc[d] = fma2(ep3, pack2(v.w, v.w), acc[d]);
            }
        }

        float da, db;
        unpack2(den2, da, db);
        ull inv2 = pack2(__fdividef(1.f, da), __fdividef(1.f, db));
        #pragma unroll
        for (int d = 0; d < NB_D; ++d)
            x2[d] = mul2(acc[d], inv2);

        __syncthreads();   // protect sKt/sVt before next block overwrites
    }

    // ---- output head: logits + log_softmax over V=5 (packed over posA/posB) ----
    ull lg2[NB_V];
    #pragma unroll
    for (int v = 0; v < NB_V; ++v)
        lg2[v] = proj1(&sWout[v][0], sBout[v], x2);

    #pragma unroll
    for (int half = 0; half < 2; ++half) {
        int pos = half == 0 ? posA : posB;
        float lg[NB_V];
        #pragma unroll
        for (int v = 0; v < NB_V; ++v) {
            float a, bb; unpack2(lg2[v], a, bb);
            lg[v] = half == 0 ? a : bb;
        }
        float mx = lg[0];
        #pragma unroll
        for (int v = 1; v < NB_V; ++v) mx = fmaxf(mx, lg[v]);
        float sum = 0.f;
        #pragma unroll
        for (int v = 0; v < NB_V; ++v) sum += __expf(lg[v] - mx);
        float lse = mx + __logf(sum);
        float* o = out + ((size_t)b * NB_S + pos) * NB_V;
        #pragma unroll
        for (int v = 0; v < NB_V; ++v) o[v] = lg[v] - lse;
    }
}

extern "C" void kernel_launch(void* const* d_in, const int* in_sizes, int n_in,
                              void* d_out, int out_size)
{
    const int*   tokens = (const int*)  d_in[0];
    const float* emb    = (const float*)d_in[1];
    const float* Wq     = (const float*)d_in[2];
    const float* bq     = (const float*)d_in[3];
    const float* Wk     = (const float*)d_in[4];
    const float* bk     = (const float*)d_in[5];
    const float* Wv     = (const float*)d_in[6];
    const float* bv     = (const float*)d_in[7];
    const float* Wout   = (const float*)d_in[8];
    const float* bout   = (const float*)d_in[9];
    float* outp = (float*)d_out;

    bert_kernel<<<NB_B, 64>>>(tokens, emb, Wq, bq, Wk, bk, Wv, bv, Wout, bout, outp);
}